// round 1
// baseline (speedup 1.0000x reference)
#include <cuda_runtime.h>

#define N_NODES 100000
#define C1 256
#define K_DIM 768
#define N_GRAPHS 512

// ---- scratch (no allocations allowed) ----
__device__ float g_deg[N_NODES];
__device__ float g_dinv[N_NODES];
__device__ float g_h1[(size_t)N_NODES * C1];    // x @ W1
__device__ float g_agg1[(size_t)N_NODES * C1];  // normalized aggregation
__device__ float g_h2[N_NODES * 2];
__device__ float g_agg2[N_NODES * 2];
__device__ float g_gsum[N_GRAPHS * 2];
__device__ float g_gcnt[N_GRAPHS];

// ---------------------------------------------------------------------------
// init: deg = 1 (self loop), zero pool accumulators
__global__ void k_init(int N) {
    int i = blockIdx.x * blockDim.x + threadIdx.x;
    if (i < N) g_deg[i] = 1.0f;
    if (i < N_GRAPHS * 2) g_gsum[i] = 0.0f;
    if (i < N_GRAPHS) g_gcnt[i] = 0.0f;
}

// deg[dst] += 1 over edges
__global__ void k_deg(const int* __restrict__ dst, int E) {
    int e = blockIdx.x * blockDim.x + threadIdx.x;
    if (e < E) atomicAdd(&g_deg[dst[e]], 1.0f);
}

__global__ void k_dinv(int N) {
    int i = blockIdx.x * blockDim.x + threadIdx.x;
    if (i < N) g_dinv[i] = rsqrtf(g_deg[i]);
}

// ---------------------------------------------------------------------------
// SGEMM: h1 = X[M,768] @ W1[768,256]; epilogue also writes agg1 = h1 * dinv^2
#define BM 128
#define BN 128
#define BK 16
#define TM 8
#define TN 8

__global__ __launch_bounds__(256, 2)
void k_gemm1(const float* __restrict__ X, const float* __restrict__ W,
             int M) {
    __shared__ float As[BK][BM];
    __shared__ float Bs[BK][BN];
    int bm = blockIdx.x * BM;
    int bn = blockIdx.y * BN;
    int tid = threadIdx.x;
    int tx = tid & 15;        // col group
    int ty = tid >> 4;        // row group
    float acc[TM][TN];
#pragma unroll
    for (int i = 0; i < TM; i++)
#pragma unroll
        for (int j = 0; j < TN; j++) acc[i][j] = 0.0f;

    for (int k0 = 0; k0 < K_DIM; k0 += BK) {
        // load A tile: BM x BK (transposed into As[k][m])
#pragma unroll
        for (int l = 0; l < 2; l++) {
            int i = tid + l * 256;            // 0..511
            int r = i >> 2;                   // 0..127
            int c4 = i & 3;                   // 0..3
            int gr = bm + r;
            float4 v = make_float4(0.f, 0.f, 0.f, 0.f);
            if (gr < M)
                v = *(const float4*)&X[(size_t)gr * K_DIM + k0 + c4 * 4];
            As[c4 * 4 + 0][r] = v.x;
            As[c4 * 4 + 1][r] = v.y;
            As[c4 * 4 + 2][r] = v.z;
            As[c4 * 4 + 3][r] = v.w;
        }
        // load B tile: BK x BN
#pragma unroll
        for (int l = 0; l < 2; l++) {
            int i = tid + l * 256;
            int r = i >> 5;                   // 0..15
            int c4 = i & 31;                  // 0..31
            float4 v = *(const float4*)&W[(size_t)(k0 + r) * C1 + bn + c4 * 4];
            *(float4*)&Bs[r][c4 * 4] = v;
        }
        __syncthreads();
#pragma unroll
        for (int k = 0; k < BK; k++) {
            float a[TM], b[TN];
#pragma unroll
            for (int i = 0; i < TM; i++) a[i] = As[k][ty * TM + i];
#pragma unroll
            for (int j = 0; j < TN; j++) b[j] = Bs[k][tx * TN + j];
#pragma unroll
            for (int i = 0; i < TM; i++)
#pragma unroll
                for (int j = 0; j < TN; j++) acc[i][j] = fmaf(a[i], b[j], acc[i][j]);
        }
        __syncthreads();
    }
    // epilogue: write h1 and agg1 = h1 * dinv^2
#pragma unroll
    for (int i = 0; i < TM; i++) {
        int gr = bm + ty * TM + i;
        if (gr >= M) continue;
        float di = g_dinv[gr];
        float self = di * di;
        size_t base = (size_t)gr * C1 + bn + tx * TN;
#pragma unroll
        for (int j = 0; j < TN; j += 4) {
            float4 v = make_float4(acc[i][j], acc[i][j + 1], acc[i][j + 2], acc[i][j + 3]);
            *(float4*)&g_h1[base + j] = v;
            float4 s = make_float4(v.x * self, v.y * self, v.z * self, v.w * self);
            *(float4*)&g_agg1[base + j] = s;
        }
    }
}

// ---------------------------------------------------------------------------
// scatter1: warp per edge. agg1[dst] += h1[src] * dinv[src]*dinv[dst]
__global__ __launch_bounds__(256)
void k_scatter1(const int* __restrict__ src, const int* __restrict__ dst, int E) {
    int warp = (blockIdx.x * blockDim.x + threadIdx.x) >> 5;
    int lane = threadIdx.x & 31;
    if (warp >= E) return;
    int s = __ldg(&src[warp]);
    int d = __ldg(&dst[warp]);
    float norm = __ldg(&g_dinv[s]) * __ldg(&g_dinv[d]);
    const float4* hs = (const float4*)&g_h1[(size_t)s * C1];
    float4* ad = (float4*)&g_agg1[(size_t)d * C1];
#pragma unroll
    for (int it = 0; it < 2; it++) {
        int c4 = lane + it * 32;
        float4 v = __ldg(&hs[c4]);
        float4 m = make_float4(v.x * norm, v.y * norm, v.z * norm, v.w * norm);
        atomicAdd(&ad[c4], m);   // red.global.add.v4.f32 (sm_90+)
    }
}

// ---------------------------------------------------------------------------
// h2 = relu(agg1 + b1) @ W2  (256 -> 2), also agg2 self-loop init
__global__ __launch_bounds__(256)
void k_h2(const float* __restrict__ b1, const float* __restrict__ W2, int N) {
    int warp = (blockIdx.x * blockDim.x + threadIdx.x) >> 5;
    int lane = threadIdx.x & 31;
    if (warp >= N) return;
    const float4* row = (const float4*)&g_agg1[(size_t)warp * C1];
    const float4* b1v = (const float4*)b1;
    const float2* w2v = (const float2*)W2;
    float d0 = 0.f, d1 = 0.f;
#pragma unroll
    for (int it = 0; it < 2; it++) {
        int c4 = lane + it * 32;
        float4 v = row[c4];
        float4 bb = __ldg(&b1v[c4]);
        float x0 = fmaxf(v.x + bb.x, 0.f);
        float x1 = fmaxf(v.y + bb.y, 0.f);
        float x2 = fmaxf(v.z + bb.z, 0.f);
        float x3 = fmaxf(v.w + bb.w, 0.f);
        float2 w0 = __ldg(&w2v[c4 * 4 + 0]);
        float2 w1 = __ldg(&w2v[c4 * 4 + 1]);
        float2 w2 = __ldg(&w2v[c4 * 4 + 2]);
        float2 w3 = __ldg(&w2v[c4 * 4 + 3]);
        d0 = fmaf(x0, w0.x, d0); d1 = fmaf(x0, w0.y, d1);
        d0 = fmaf(x1, w1.x, d0); d1 = fmaf(x1, w1.y, d1);
        d0 = fmaf(x2, w2.x, d0); d1 = fmaf(x2, w2.y, d1);
        d0 = fmaf(x3, w3.x, d0); d1 = fmaf(x3, w3.y, d1);
    }
#pragma unroll
    for (int off = 16; off; off >>= 1) {
        d0 += __shfl_down_sync(0xFFFFFFFFu, d0, off);
        d1 += __shfl_down_sync(0xFFFFFFFFu, d1, off);
    }
    if (lane == 0) {
        float di = g_dinv[warp];
        float self = di * di;
        *(float2*)&g_h2[warp * 2] = make_float2(d0, d1);
        *(float2*)&g_agg2[warp * 2] = make_float2(d0 * self, d1 * self);
    }
}

// scatter2: thread per edge, 2 floats
__global__ __launch_bounds__(256)
void k_scatter2(const int* __restrict__ src, const int* __restrict__ dst, int E) {
    int e = blockIdx.x * blockDim.x + threadIdx.x;
    if (e >= E) return;
    int s = __ldg(&src[e]);
    int d = __ldg(&dst[e]);
    float norm = __ldg(&g_dinv[s]) * __ldg(&g_dinv[d]);
    float2 h = *(const float2*)&g_h2[s * 2];
    atomicAdd((float2*)&g_agg2[d * 2], make_float2(h.x * norm, h.y * norm));
}

// pool: per-node atomics into per-graph sums + counts
__global__ __launch_bounds__(256)
void k_pool(const int* __restrict__ batch, int N) {
    int n = blockIdx.x * blockDim.x + threadIdx.x;
    if (n >= N) return;
    int g = __ldg(&batch[n]);
    float2 v = *(const float2*)&g_agg2[n * 2];
    atomicAdd(&g_gsum[g * 2 + 0], v.x);
    atomicAdd(&g_gsum[g * 2 + 1], v.y);
    atomicAdd(&g_gcnt[g], 1.0f);
}

// finalize: mean + b2
__global__ void k_final(const float* __restrict__ b2, float* __restrict__ out) {
    int g = blockIdx.x * blockDim.x + threadIdx.x;
    if (g >= N_GRAPHS) return;
    float c = fmaxf(g_gcnt[g], 1.0f);
    out[g * 2 + 0] = g_gsum[g * 2 + 0] / c + b2[0];
    out[g * 2 + 1] = g_gsum[g * 2 + 1] / c + b2[1];
}

// ---------------------------------------------------------------------------
extern "C" void kernel_launch(void* const* d_in, const int* in_sizes, int n_in,
                              void* d_out, int out_size) {
    const float* x     = (const float*)d_in[0];
    const int*   ei    = (const int*)d_in[1];
    const int*   batch = (const int*)d_in[2];
    const float* W1    = (const float*)d_in[3];
    const float* b1    = (const float*)d_in[4];
    const float* W2    = (const float*)d_in[5];
    const float* b2    = (const float*)d_in[6];
    float* out = (float*)d_out;

    int N = in_sizes[0] / K_DIM;     // 100000
    int E = in_sizes[1] / 2;         // 1600000
    const int* src = ei;
    const int* dst = ei + E;

    // degrees
    k_init<<<(N + 255) / 256, 256>>>(N);
    k_deg<<<(E + 255) / 256, 256>>>(dst, E);
    k_dinv<<<(N + 255) / 256, 256>>>(N);

    // layer 1 GEMM + self-loop epilogue
    dim3 g1((N + BM - 1) / BM, C1 / BN);
    k_gemm1<<<g1, 256>>>(x, W1, N);

    // layer 1 edge aggregation (warp per edge)
    long long warps1 = (long long)E;
    k_scatter1<<<(int)((warps1 * 32 + 255) / 256), 256>>>(src, dst, E);

    // relu + b1 + GEMM2 + agg2 self init (warp per node)
    k_h2<<<(int)(((long long)N * 32 + 255) / 256), 256>>>(b1, W2, N);

    // layer 2 edge aggregation
    k_scatter2<<<(E + 255) / 256, 256>>>(src, dst, E);

    // pooling
    k_pool<<<(N + 255) / 256, 256>>>(batch, N);
    k_final<<<(N_GRAPHS + 255) / 256, 256>>>(b2, out);
}

// round 2
// speedup vs baseline: 1.7536x; 1.7536x over previous
#include <cuda_runtime.h>
#include <cstdint>

#define N_NODES 100000
#define C1 256
#define K_DIM 768
#define N_GRAPHS 512

// ---- scratch (no allocations allowed) ----
__device__ float g_deg[N_NODES];
__device__ float g_dinv[N_NODES];
__device__ float g_h1[(size_t)N_NODES * C1];    // x @ W1
__device__ float g_agg1[(size_t)N_NODES * C1];  // normalized aggregation
__device__ float g_h2[N_NODES * 2];
__device__ float g_agg2[N_NODES * 2];
__device__ float g_gsum[N_GRAPHS * 2];
__device__ float g_gcnt[N_GRAPHS];

// ---------------------------------------------------------------------------
__global__ void k_init(int N) {
    int i = blockIdx.x * blockDim.x + threadIdx.x;
    if (i < N) g_deg[i] = 1.0f;
    if (i < N_GRAPHS * 2) g_gsum[i] = 0.0f;
    if (i < N_GRAPHS) g_gcnt[i] = 0.0f;
}

__global__ void k_deg(const int* __restrict__ dst, int E) {
    int e = blockIdx.x * blockDim.x + threadIdx.x;
    if (e < E) atomicAdd(&g_deg[dst[e]], 1.0f);
}

__global__ void k_dinv(int N) {
    int i = blockIdx.x * blockDim.x + threadIdx.x;
    if (i < N) g_dinv[i] = rsqrtf(g_deg[i]);
}

// ---------------------------------------------------------------------------
// TF32 tensor-core GEMM: h1 = X[M,768] @ W1[768,256]
// BM=128, BN=128, BK=16, 8 warps (4x2), warp tile 32x64, m16n8k8 atoms.
// Epilogue writes h1 and agg1 = h1 * dinv^2.
#define BM 128
#define BN 128
#define BK 16

__global__ __launch_bounds__(256, 2)
void k_gemm1(const float* __restrict__ X, const float* __restrict__ W, int M) {
    __shared__ float As[2][BM][BK + 4];   // row-major [m][k], stride 20 fl = 80B (16B-mult)
    __shared__ float Bs[2][BK][BN + 4];   // row-major [k][n], stride 132 fl = 528B

    const int tid  = threadIdx.x;
    const int lane = tid & 31;
    const int warp = tid >> 5;
    const int wm = warp & 3;          // 0..3  (M)
    const int wn = warp >> 2;         // 0..1  (N)
    const int bm = blockIdx.x * BM;
    const int bn = blockIdx.y * BN;

    float acc[2][8][4];
#pragma unroll
    for (int i = 0; i < 2; i++)
#pragma unroll
        for (int j = 0; j < 8; j++)
#pragma unroll
            for (int t = 0; t < 4; t++) acc[i][j][t] = 0.0f;

    const int NS = K_DIM / BK;  // 48

    auto load_stage = [&](int s, int buf) {
        int k0 = s * BK;
        // A tile: 128x16 = 512 float4, 2 per thread
#pragma unroll
        for (int l = 0; l < 2; l++) {
            int idx = tid + l * 256;
            int row = idx >> 2;
            int ch  = idx & 3;
            int gr  = bm + row;
            int sz  = (gr < M) ? 16 : 0;
            if (gr >= M) gr = M - 1;  // keep address valid; sz=0 zero-fills
            const float* src = X + (size_t)gr * K_DIM + k0 + ch * 4;
            uint32_t dst = (uint32_t)__cvta_generic_to_shared(&As[buf][row][ch * 4]);
            asm volatile("cp.async.cg.shared.global [%0], [%1], 16, %2;\n"
                         :: "r"(dst), "l"(src), "r"(sz));
        }
        // B tile: 16x128 = 512 float4, 2 per thread
#pragma unroll
        for (int l = 0; l < 2; l++) {
            int idx = tid + l * 256;
            int row = idx >> 5;
            int ch  = idx & 31;
            const float* src = W + (size_t)(k0 + row) * C1 + bn + ch * 4;
            uint32_t dst = (uint32_t)__cvta_generic_to_shared(&Bs[buf][row][ch * 4]);
            asm volatile("cp.async.cg.shared.global [%0], [%1], 16;\n"
                         :: "r"(dst), "l"(src));
        }
        asm volatile("cp.async.commit_group;\n");
    };

    load_stage(0, 0);

    for (int s = 0; s < NS; s++) {
        int buf = s & 1;
        if (s + 1 < NS) {
            load_stage(s + 1, (s + 1) & 1);
            asm volatile("cp.async.wait_group 1;\n");
        } else {
            asm volatile("cp.async.wait_group 0;\n");
        }
        __syncthreads();

#pragma unroll
        for (int kk = 0; kk < 2; kk++) {
            uint32_t a[2][4], b[8][2];
#pragma unroll
            for (int i = 0; i < 2; i++) {
                int r = wm * 32 + i * 16 + (lane >> 2);
                int c = kk * 8 + (lane & 3);
                asm("cvt.rna.tf32.f32 %0, %1;" : "=r"(a[i][0]) : "f"(As[buf][r][c]));
                asm("cvt.rna.tf32.f32 %0, %1;" : "=r"(a[i][1]) : "f"(As[buf][r + 8][c]));
                asm("cvt.rna.tf32.f32 %0, %1;" : "=r"(a[i][2]) : "f"(As[buf][r][c + 4]));
                asm("cvt.rna.tf32.f32 %0, %1;" : "=r"(a[i][3]) : "f"(As[buf][r + 8][c + 4]));
            }
#pragma unroll
            for (int j = 0; j < 8; j++) {
                int rb = kk * 8 + (lane & 3);
                int cb = wn * 64 + j * 8 + (lane >> 2);
                asm("cvt.rna.tf32.f32 %0, %1;" : "=r"(b[j][0]) : "f"(Bs[buf][rb][cb]));
                asm("cvt.rna.tf32.f32 %0, %1;" : "=r"(b[j][1]) : "f"(Bs[buf][rb + 4][cb]));
            }
#pragma unroll
            for (int i = 0; i < 2; i++)
#pragma unroll
                for (int j = 0; j < 8; j++)
                    asm volatile(
                        "mma.sync.aligned.m16n8k8.row.col.f32.tf32.tf32.f32 "
                        "{%0,%1,%2,%3}, {%4,%5,%6,%7}, {%8,%9}, {%0,%1,%2,%3};\n"
                        : "+f"(acc[i][j][0]), "+f"(acc[i][j][1]),
                          "+f"(acc[i][j][2]), "+f"(acc[i][j][3])
                        : "r"(a[i][0]), "r"(a[i][1]), "r"(a[i][2]), "r"(a[i][3]),
                          "r"(b[j][0]), "r"(b[j][1]));
        }
        __syncthreads();
    }

    // epilogue: c0,c1 at (row, 2*(lane&3)), c2,c3 at (row+8, ...)
#pragma unroll
    for (int i = 0; i < 2; i++) {
        int gr0 = bm + wm * 32 + i * 16 + (lane >> 2);
        int gr1 = gr0 + 8;
        bool v0 = gr0 < M, v1 = gr1 < M;
        float s0 = 0.f, s1 = 0.f;
        if (v0) { float d = g_dinv[gr0]; s0 = d * d; }
        if (v1) { float d = g_dinv[gr1]; s1 = d * d; }
#pragma unroll
        for (int j = 0; j < 8; j++) {
            int col = bn + wn * 64 + j * 8 + 2 * (lane & 3);
            if (v0) {
                size_t o = (size_t)gr0 * C1 + col;
                *(float2*)&g_h1[o]   = make_float2(acc[i][j][0], acc[i][j][1]);
                *(float2*)&g_agg1[o] = make_float2(acc[i][j][0] * s0, acc[i][j][1] * s0);
            }
            if (v1) {
                size_t o = (size_t)gr1 * C1 + col;
                *(float2*)&g_h1[o]   = make_float2(acc[i][j][2], acc[i][j][3]);
                *(float2*)&g_agg1[o] = make_float2(acc[i][j][2] * s1, acc[i][j][3] * s1);
            }
        }
    }
}

// ---------------------------------------------------------------------------
// scatter1: warp per edge. agg1[dst] += h1[src] * dinv[src]*dinv[dst]
__global__ __launch_bounds__(256)
void k_scatter1(const int* __restrict__ src, const int* __restrict__ dst, int E) {
    int warp = (blockIdx.x * blockDim.x + threadIdx.x) >> 5;
    int lane = threadIdx.x & 31;
    if (warp >= E) return;
    int s = __ldg(&src[warp]);
    int d = __ldg(&dst[warp]);
    float norm = __ldg(&g_dinv[s]) * __ldg(&g_dinv[d]);
    const float4* hs = (const float4*)&g_h1[(size_t)s * C1];
    float4* ad = (float4*)&g_agg1[(size_t)d * C1];
#pragma unroll
    for (int it = 0; it < 2; it++) {
        int c4 = lane + it * 32;
        float4 v = __ldg(&hs[c4]);
        float4 m = make_float4(v.x * norm, v.y * norm, v.z * norm, v.w * norm);
        atomicAdd(&ad[c4], m);
    }
}

// ---------------------------------------------------------------------------
// h2 = relu(agg1 + b1) @ W2  (256 -> 2), also agg2 self-loop init
__global__ __launch_bounds__(256)
void k_h2(const float* __restrict__ b1, const float* __restrict__ W2, int N) {
    int warp = (blockIdx.x * blockDim.x + threadIdx.x) >> 5;
    int lane = threadIdx.x & 31;
    if (warp >= N) return;
    const float4* row = (const float4*)&g_agg1[(size_t)warp * C1];
    const float4* b1v = (const float4*)b1;
    const float2* w2v = (const float2*)W2;
    float d0 = 0.f, d1 = 0.f;
#pragma unroll
    for (int it = 0; it < 2; it++) {
        int c4 = lane + it * 32;
        float4 v = row[c4];
        float4 bb = __ldg(&b1v[c4]);
        float x0 = fmaxf(v.x + bb.x, 0.f);
        float x1 = fmaxf(v.y + bb.y, 0.f);
        float x2 = fmaxf(v.z + bb.z, 0.f);
        float x3 = fmaxf(v.w + bb.w, 0.f);
        float2 w0 = __ldg(&w2v[c4 * 4 + 0]);
        float2 w1 = __ldg(&w2v[c4 * 4 + 1]);
        float2 w2 = __ldg(&w2v[c4 * 4 + 2]);
        float2 w3 = __ldg(&w2v[c4 * 4 + 3]);
        d0 = fmaf(x0, w0.x, d0); d1 = fmaf(x0, w0.y, d1);
        d0 = fmaf(x1, w1.x, d0); d1 = fmaf(x1, w1.y, d1);
        d0 = fmaf(x2, w2.x, d0); d1 = fmaf(x2, w2.y, d1);
        d0 = fmaf(x3, w3.x, d0); d1 = fmaf(x3, w3.y, d1);
    }
#pragma unroll
    for (int off = 16; off; off >>= 1) {
        d0 += __shfl_down_sync(0xFFFFFFFFu, d0, off);
        d1 += __shfl_down_sync(0xFFFFFFFFu, d1, off);
    }
    if (lane == 0) {
        float di = g_dinv[warp];
        float self = di * di;
        *(float2*)&g_h2[warp * 2] = make_float2(d0, d1);
        *(float2*)&g_agg2[warp * 2] = make_float2(d0 * self, d1 * self);
    }
}

// scatter2: thread per edge, 2 floats
__global__ __launch_bounds__(256)
void k_scatter2(const int* __restrict__ src, const int* __restrict__ dst, int E) {
    int e = blockIdx.x * blockDim.x + threadIdx.x;
    if (e >= E) return;
    int s = __ldg(&src[e]);
    int d = __ldg(&dst[e]);
    float norm = __ldg(&g_dinv[s]) * __ldg(&g_dinv[d]);
    float2 h = *(const float2*)&g_h2[s * 2];
    atomicAdd((float2*)&g_agg2[d * 2], make_float2(h.x * norm, h.y * norm));
}

// pool
__global__ __launch_bounds__(256)
void k_pool(const int* __restrict__ batch, int N) {
    int n = blockIdx.x * blockDim.x + threadIdx.x;
    if (n >= N) return;
    int g = __ldg(&batch[n]);
    float2 v = *(const float2*)&g_agg2[n * 2];
    atomicAdd(&g_gsum[g * 2 + 0], v.x);
    atomicAdd(&g_gsum[g * 2 + 1], v.y);
    atomicAdd(&g_gcnt[g], 1.0f);
}

__global__ void k_final(const float* __restrict__ b2, float* __restrict__ out) {
    int g = blockIdx.x * blockDim.x + threadIdx.x;
    if (g >= N_GRAPHS) return;
    float c = fmaxf(g_gcnt[g], 1.0f);
    out[g * 2 + 0] = g_gsum[g * 2 + 0] / c + b2[0];
    out[g * 2 + 1] = g_gsum[g * 2 + 1] / c + b2[1];
}

// ---------------------------------------------------------------------------
extern "C" void kernel_launch(void* const* d_in, const int* in_sizes, int n_in,
                              void* d_out, int out_size) {
    const float* x     = (const float*)d_in[0];
    const int*   ei    = (const int*)d_in[1];
    const int*   batch = (const int*)d_in[2];
    const float* W1    = (const float*)d_in[3];
    const float* b1    = (const float*)d_in[4];
    const float* W2    = (const float*)d_in[5];
    const float* b2    = (const float*)d_in[6];
    float* out = (float*)d_out;

    int N = in_sizes[0] / K_DIM;     // 100000
    int E = in_sizes[1] / 2;         // 1600000
    const int* src = ei;
    const int* dst = ei + E;

    k_init<<<(N + 255) / 256, 256>>>(N);
    k_deg<<<(E + 255) / 256, 256>>>(dst, E);
    k_dinv<<<(N + 255) / 256, 256>>>(N);

    dim3 g1((N + BM - 1) / BM, C1 / BN);
    k_gemm1<<<g1, 256>>>(x, W1, N);

    long long warps1 = (long long)E;
    k_scatter1<<<(int)((warps1 * 32 + 255) / 256), 256>>>(src, dst, E);

    k_h2<<<(int)(((long long)N * 32 + 255) / 256), 256>>>(b1, W2, N);

    k_scatter2<<<(E + 255) / 256, 256>>>(src, dst, E);

    k_pool<<<(N + 255) / 256, 256>>>(batch, N);
    k_final<<<(N_GRAPHS + 255) / 256, 256>>>(b2, out);
}

// round 3
// speedup vs baseline: 2.7748x; 1.5824x over previous
#include <cuda_runtime.h>
#include <cstdint>

#define N_NODES 100000
#define C1 256
#define K_DIM 768
#define N_GRAPHS 512
#define MAX_EDGES 1600000

// ---- scratch (no allocations allowed) ----
__device__ float g_dinv[N_NODES];
__device__ float g_h1[(size_t)N_NODES * C1];    // x @ W1
__device__ float g_h2[N_NODES * 2];
__device__ float g_gsum[N_GRAPHS * 2];
__device__ float g_gcnt[N_GRAPHS];
// CSR build
__device__ int g_cnt[N_NODES];          // in-degree histogram (no self loop)
__device__ int g_cur[N_NODES];          // placement cursors
__device__ int g_off[N_NODES + 1];      // exclusive scan offsets
__device__ int g_csr[MAX_EDGES];        // src list grouped by dst
__device__ int g_bsum[128];             // block sums for scan
__device__ int g_boff[128];             // scanned block offsets

// ---------------------------------------------------------------------------
__global__ void k_init(int N) {
    int i = blockIdx.x * blockDim.x + threadIdx.x;
    if (i < N) { g_cnt[i] = 0; g_cur[i] = 0; }
    if (i < N_GRAPHS * 2) g_gsum[i] = 0.0f;
    if (i < N_GRAPHS) g_gcnt[i] = 0.0f;
}

__global__ void k_hist(const int* __restrict__ dst, int E) {
    int e = blockIdx.x * blockDim.x + threadIdx.x;
    if (e < E) atomicAdd(&g_cnt[dst[e]], 1);
}

__global__ void k_dinv(int N) {
    int i = blockIdx.x * blockDim.x + threadIdx.x;
    if (i < N) g_dinv[i] = rsqrtf((float)g_cnt[i] + 1.0f);
}

// ---- two-level exclusive scan of g_cnt -> g_off -----------------------------
// level A: block sums (1024 elements per block, 256 threads x 4)
__global__ void k_bsum(int N) {
    __shared__ int sm[256];
    int b = blockIdx.x, t = threadIdx.x;
    int base = b * 1024 + t * 4;
    int s = 0;
#pragma unroll
    for (int j = 0; j < 4; j++) {
        int idx = base + j;
        if (idx < N) s += g_cnt[idx];
    }
    sm[t] = s;
    __syncthreads();
    for (int o = 128; o; o >>= 1) {
        if (t < o) sm[t] += sm[t + o];
        __syncthreads();
    }
    if (t == 0) g_bsum[b] = sm[0];
}

// level B: scan block sums (single thread; NB <= 128)
__global__ void k_top(int NB, int N) {
    if (threadIdx.x == 0 && blockIdx.x == 0) {
        int run = 0;
        for (int i = 0; i < NB; i++) { g_boff[i] = run; run += g_bsum[i]; }
        g_off[N] = run;
    }
}

// level C: per-block exclusive scan + add block offset
__global__ void k_scan(int N) {
    __shared__ int warp_tot[8];
    int b = blockIdx.x, t = threadIdx.x;
    int lane = t & 31, wid = t >> 5;
    int base = b * 1024 + t * 4;
    int v[4];
#pragma unroll
    for (int j = 0; j < 4; j++) {
        int idx = base + j;
        v[j] = (idx < N) ? g_cnt[idx] : 0;
    }
    int tsum = v[0] + v[1] + v[2] + v[3];
    // warp inclusive scan of tsum
    int incl = tsum;
#pragma unroll
    for (int o = 1; o < 32; o <<= 1) {
        int n = __shfl_up_sync(0xFFFFFFFFu, incl, o);
        if (lane >= o) incl += n;
    }
    if (lane == 31) warp_tot[wid] = incl;
    __syncthreads();
    if (wid == 0 && lane < 8) {
        int w = warp_tot[lane];
        int wi = w;
#pragma unroll
        for (int o = 1; o < 8; o <<= 1) {
            int n = __shfl_up_sync(0xFFu, wi, o);
            if (lane >= o) wi += n;
        }
        warp_tot[lane] = wi - w;   // exclusive
    }
    __syncthreads();
    int texcl = warp_tot[wid] + (incl - tsum) + g_boff[b];
    int run = texcl;
#pragma unroll
    for (int j = 0; j < 4; j++) {
        int idx = base + j;
        if (idx < N) g_off[idx] = run;
        run += v[j];
    }
}

__global__ void k_place(const int* __restrict__ src, const int* __restrict__ dst, int E) {
    int e = blockIdx.x * blockDim.x + threadIdx.x;
    if (e >= E) return;
    int d = dst[e];
    int pos = g_off[d] + atomicAdd(&g_cur[d], 1);
    g_csr[pos] = src[e];
}

// ---------------------------------------------------------------------------
// TF32 tensor-core GEMM: h1 = X[M,768] @ W1[768,256]
#define BM 128
#define BN 128
#define BK 16

__global__ __launch_bounds__(256, 2)
void k_gemm1(const float* __restrict__ X, const float* __restrict__ W, int M) {
    __shared__ float As[2][BM][BK + 4];
    __shared__ float Bs[2][BK][BN + 4];

    const int tid  = threadIdx.x;
    const int lane = tid & 31;
    const int warp = tid >> 5;
    const int wm = warp & 3;
    const int wn = warp >> 2;
    const int bm = blockIdx.x * BM;
    const int bn = blockIdx.y * BN;

    float acc[2][8][4];
#pragma unroll
    for (int i = 0; i < 2; i++)
#pragma unroll
        for (int j = 0; j < 8; j++)
#pragma unroll
            for (int t = 0; t < 4; t++) acc[i][j][t] = 0.0f;

    const int NS = K_DIM / BK;  // 48

    auto load_stage = [&](int s, int buf) {
        int k0 = s * BK;
#pragma unroll
        for (int l = 0; l < 2; l++) {
            int idx = tid + l * 256;
            int row = idx >> 2;
            int ch  = idx & 3;
            int gr  = bm + row;
            int sz  = (gr < M) ? 16 : 0;
            if (gr >= M) gr = M - 1;
            const float* srcp = X + (size_t)gr * K_DIM + k0 + ch * 4;
            uint32_t dstp = (uint32_t)__cvta_generic_to_shared(&As[buf][row][ch * 4]);
            asm volatile("cp.async.cg.shared.global [%0], [%1], 16, %2;\n"
                         :: "r"(dstp), "l"(srcp), "r"(sz));
        }
#pragma unroll
        for (int l = 0; l < 2; l++) {
            int idx = tid + l * 256;
            int row = idx >> 5;
            int ch  = idx & 31;
            const float* srcp = W + (size_t)(k0 + row) * C1 + bn + ch * 4;
            uint32_t dstp = (uint32_t)__cvta_generic_to_shared(&Bs[buf][row][ch * 4]);
            asm volatile("cp.async.cg.shared.global [%0], [%1], 16;\n"
                         :: "r"(dstp), "l"(srcp));
        }
        asm volatile("cp.async.commit_group;\n");
    };

    load_stage(0, 0);

    for (int s = 0; s < NS; s++) {
        int buf = s & 1;
        if (s + 1 < NS) {
            load_stage(s + 1, (s + 1) & 1);
            asm volatile("cp.async.wait_group 1;\n");
        } else {
            asm volatile("cp.async.wait_group 0;\n");
        }
        __syncthreads();

#pragma unroll
        for (int kk = 0; kk < 2; kk++) {
            uint32_t a[2][4], b[8][2];
#pragma unroll
            for (int i = 0; i < 2; i++) {
                int r = wm * 32 + i * 16 + (lane >> 2);
                int c = kk * 8 + (lane & 3);
                asm("cvt.rna.tf32.f32 %0, %1;" : "=r"(a[i][0]) : "f"(As[buf][r][c]));
                asm("cvt.rna.tf32.f32 %0, %1;" : "=r"(a[i][1]) : "f"(As[buf][r + 8][c]));
                asm("cvt.rna.tf32.f32 %0, %1;" : "=r"(a[i][2]) : "f"(As[buf][r][c + 4]));
                asm("cvt.rna.tf32.f32 %0, %1;" : "=r"(a[i][3]) : "f"(As[buf][r + 8][c + 4]));
            }
#pragma unroll
            for (int j = 0; j < 8; j++) {
                int rb = kk * 8 + (lane & 3);
                int cb = wn * 64 + j * 8 + (lane >> 2);
                asm("cvt.rna.tf32.f32 %0, %1;" : "=r"(b[j][0]) : "f"(Bs[buf][rb][cb]));
                asm("cvt.rna.tf32.f32 %0, %1;" : "=r"(b[j][1]) : "f"(Bs[buf][rb + 4][cb]));
            }
#pragma unroll
            for (int i = 0; i < 2; i++)
#pragma unroll
                for (int j = 0; j < 8; j++)
                    asm volatile(
                        "mma.sync.aligned.m16n8k8.row.col.f32.tf32.tf32.f32 "
                        "{%0,%1,%2,%3}, {%4,%5,%6,%7}, {%8,%9}, {%0,%1,%2,%3};\n"
                        : "+f"(acc[i][j][0]), "+f"(acc[i][j][1]),
                          "+f"(acc[i][j][2]), "+f"(acc[i][j][3])
                        : "r"(a[i][0]), "r"(a[i][1]), "r"(a[i][2]), "r"(a[i][3]),
                          "r"(b[j][0]), "r"(b[j][1]));
        }
        __syncthreads();
    }

#pragma unroll
    for (int i = 0; i < 2; i++) {
        int gr0 = bm + wm * 32 + i * 16 + (lane >> 2);
        int gr1 = gr0 + 8;
        bool v0 = gr0 < M, v1 = gr1 < M;
#pragma unroll
        for (int j = 0; j < 8; j++) {
            int col = bn + wn * 64 + j * 8 + 2 * (lane & 3);
            if (v0)
                *(float2*)&g_h1[(size_t)gr0 * C1 + col] = make_float2(acc[i][j][0], acc[i][j][1]);
            if (v1)
                *(float2*)&g_h1[(size_t)gr1 * C1 + col] = make_float2(acc[i][j][2], acc[i][j][3]);
        }
    }
}

// ---------------------------------------------------------------------------
// Fused layer-1 aggregation + ReLU + bias + GEMM2 (256->2).
// Warp per node: register accumulation over incoming edges (no atomics).
__global__ __launch_bounds__(256)
void k_agg1h2(const float* __restrict__ b1, const float* __restrict__ W2, int N) {
    int node = (blockIdx.x * blockDim.x + threadIdx.x) >> 5;
    int lane = threadIdx.x & 31;
    if (node >= N) return;

    float dn = g_dinv[node];
    float self = dn * dn;

    // lane owns float4 chunks [lane] and [lane+32] of the 64-float4 row
    const float4* hrow = (const float4*)&g_h1[(size_t)node * C1];
    float4 a0 = __ldg(&hrow[lane]);
    float4 a1 = __ldg(&hrow[lane + 32]);
    float4 acc0 = make_float4(a0.x * self, a0.y * self, a0.z * self, a0.w * self);
    float4 acc1 = make_float4(a1.x * self, a1.y * self, a1.z * self, a1.w * self);
    float4 bcc0 = make_float4(0.f, 0.f, 0.f, 0.f);
    float4 bcc1 = make_float4(0.f, 0.f, 0.f, 0.f);

    int beg = g_off[node];
    int end = g_off[node + 1];
    int e = beg;
    for (; e + 1 < end; e += 2) {
        int s0 = __ldg(&g_csr[e]);
        int s1 = __ldg(&g_csr[e + 1]);
        float n0 = __ldg(&g_dinv[s0]) * dn;
        float n1 = __ldg(&g_dinv[s1]) * dn;
        const float4* r0 = (const float4*)&g_h1[(size_t)s0 * C1];
        const float4* r1 = (const float4*)&g_h1[(size_t)s1 * C1];
        float4 p0 = __ldg(&r0[lane]);
        float4 p1 = __ldg(&r0[lane + 32]);
        float4 q0 = __ldg(&r1[lane]);
        float4 q1 = __ldg(&r1[lane + 32]);
        acc0.x = fmaf(p0.x, n0, acc0.x); acc0.y = fmaf(p0.y, n0, acc0.y);
        acc0.z = fmaf(p0.z, n0, acc0.z); acc0.w = fmaf(p0.w, n0, acc0.w);
        acc1.x = fmaf(p1.x, n0, acc1.x); acc1.y = fmaf(p1.y, n0, acc1.y);
        acc1.z = fmaf(p1.z, n0, acc1.z); acc1.w = fmaf(p1.w, n0, acc1.w);
        bcc0.x = fmaf(q0.x, n1, bcc0.x); bcc0.y = fmaf(q0.y, n1, bcc0.y);
        bcc0.z = fmaf(q0.z, n1, bcc0.z); bcc0.w = fmaf(q0.w, n1, bcc0.w);
        bcc1.x = fmaf(q1.x, n1, bcc1.x); bcc1.y = fmaf(q1.y, n1, bcc1.y);
        bcc1.z = fmaf(q1.z, n1, bcc1.z); bcc1.w = fmaf(q1.w, n1, bcc1.w);
    }
    if (e < end) {
        int s0 = __ldg(&g_csr[e]);
        float n0 = __ldg(&g_dinv[s0]) * dn;
        const float4* r0 = (const float4*)&g_h1[(size_t)s0 * C1];
        float4 p0 = __ldg(&r0[lane]);
        float4 p1 = __ldg(&r0[lane + 32]);
        acc0.x = fmaf(p0.x, n0, acc0.x); acc0.y = fmaf(p0.y, n0, acc0.y);
        acc0.z = fmaf(p0.z, n0, acc0.z); acc0.w = fmaf(p0.w, n0, acc0.w);
        acc1.x = fmaf(p1.x, n0, acc1.x); acc1.y = fmaf(p1.y, n0, acc1.y);
        acc1.z = fmaf(p1.z, n0, acc1.z); acc1.w = fmaf(p1.w, n0, acc1.w);
    }
    acc0.x += bcc0.x; acc0.y += bcc0.y; acc0.z += bcc0.z; acc0.w += bcc0.w;
    acc1.x += bcc1.x; acc1.y += bcc1.y; acc1.z += bcc1.z; acc1.w += bcc1.w;

    // bias + relu + 256->2 GEMM: lane covers cols [4*lane,4*lane+4) and +128
    const float4* b1v = (const float4*)b1;
    float4 bb0 = __ldg(&b1v[lane]);
    float4 bb1 = __ldg(&b1v[lane + 32]);
    float x0 = fmaxf(acc0.x + bb0.x, 0.f);
    float x1 = fmaxf(acc0.y + bb0.y, 0.f);
    float x2 = fmaxf(acc0.z + bb0.z, 0.f);
    float x3 = fmaxf(acc0.w + bb0.w, 0.f);
    float y0 = fmaxf(acc1.x + bb1.x, 0.f);
    float y1 = fmaxf(acc1.y + bb1.y, 0.f);
    float y2 = fmaxf(acc1.z + bb1.z, 0.f);
    float y3 = fmaxf(acc1.w + bb1.w, 0.f);

    const float2* w2v = (const float2*)W2;
    float d0 = 0.f, d1 = 0.f;
    float2 w;
    w = __ldg(&w2v[4 * lane + 0]);       d0 = fmaf(x0, w.x, d0); d1 = fmaf(x0, w.y, d1);
    w = __ldg(&w2v[4 * lane + 1]);       d0 = fmaf(x1, w.x, d0); d1 = fmaf(x1, w.y, d1);
    w = __ldg(&w2v[4 * lane + 2]);       d0 = fmaf(x2, w.x, d0); d1 = fmaf(x2, w.y, d1);
    w = __ldg(&w2v[4 * lane + 3]);       d0 = fmaf(x3, w.x, d0); d1 = fmaf(x3, w.y, d1);
    w = __ldg(&w2v[128 + 4 * lane + 0]); d0 = fmaf(y0, w.x, d0); d1 = fmaf(y0, w.y, d1);
    w = __ldg(&w2v[128 + 4 * lane + 1]); d0 = fmaf(y1, w.x, d0); d1 = fmaf(y1, w.y, d1);
    w = __ldg(&w2v[128 + 4 * lane + 2]); d0 = fmaf(y2, w.x, d0); d1 = fmaf(y2, w.y, d1);
    w = __ldg(&w2v[128 + 4 * lane + 3]); d0 = fmaf(y3, w.x, d0); d1 = fmaf(y3, w.y, d1);

#pragma unroll
    for (int off = 16; off; off >>= 1) {
        d0 += __shfl_down_sync(0xFFFFFFFFu, d0, off);
        d1 += __shfl_down_sync(0xFFFFFFFFu, d1, off);
    }
    if (lane == 0)
        *(float2*)&g_h2[node * 2] = make_float2(d0, d1);
}

// ---------------------------------------------------------------------------
// Fused layer-2 aggregation + mean-pool accumulation. Thread per node.
__global__ __launch_bounds__(256)
void k_agg2pool(const int* __restrict__ batch, int N) {
    int n = blockIdx.x * blockDim.x + threadIdx.x;
    if (n >= N) return;
    float dn = g_dinv[n];
    float2 h = *(const float2*)&g_h2[n * 2];
    float a0 = h.x * dn * dn;
    float a1 = h.y * dn * dn;
    int beg = g_off[n], end = g_off[n + 1];
    for (int e = beg; e < end; e++) {
        int s = __ldg(&g_csr[e]);
        float norm = __ldg(&g_dinv[s]) * dn;
        float2 hs = *(const float2*)&g_h2[s * 2];
        a0 = fmaf(hs.x, norm, a0);
        a1 = fmaf(hs.y, norm, a1);
    }
    int g = __ldg(&batch[n]);
    atomicAdd(&g_gsum[g * 2 + 0], a0);
    atomicAdd(&g_gsum[g * 2 + 1], a1);
    atomicAdd(&g_gcnt[g], 1.0f);
}

__global__ void k_final(const float* __restrict__ b2, float* __restrict__ out) {
    int g = blockIdx.x * blockDim.x + threadIdx.x;
    if (g >= N_GRAPHS) return;
    float c = fmaxf(g_gcnt[g], 1.0f);
    out[g * 2 + 0] = g_gsum[g * 2 + 0] / c + b2[0];
    out[g * 2 + 1] = g_gsum[g * 2 + 1] / c + b2[1];
}

// ---------------------------------------------------------------------------
extern "C" void kernel_launch(void* const* d_in, const int* in_sizes, int n_in,
                              void* d_out, int out_size) {
    const float* x     = (const float*)d_in[0];
    const int*   ei    = (const int*)d_in[1];
    const int*   batch = (const int*)d_in[2];
    const float* W1    = (const float*)d_in[3];
    const float* b1    = (const float*)d_in[4];
    const float* W2    = (const float*)d_in[5];
    const float* b2    = (const float*)d_in[6];
    float* out = (float*)d_out;

    int N = in_sizes[0] / K_DIM;     // 100000
    int E = in_sizes[1] / 2;         // 1600000
    const int* src = ei;
    const int* dst = ei + E;

    int NB = (N + 1023) / 1024;      // scan blocks (98)

    k_init<<<(N + 255) / 256, 256>>>(N);
    k_hist<<<(E + 255) / 256, 256>>>(dst, E);
    k_dinv<<<(N + 255) / 256, 256>>>(N);

    // CSR build
    k_bsum<<<NB, 256>>>(N);
    k_top<<<1, 32>>>(NB, N);
    k_scan<<<NB, 256>>>(N);
    k_place<<<(E + 255) / 256, 256>>>(src, dst, E);

    // layer 1 GEMM (runs while CSR builds are independent of it on same stream;
    // serialized by stream order, but all are cheap)
    dim3 g1((N + BM - 1) / BM, C1 / BN);
    k_gemm1<<<g1, 256>>>(x, W1, N);

    // fused aggregation + relu + bias + GEMM2
    k_agg1h2<<<(int)(((long long)N * 32 + 255) / 256), 256>>>(b1, W2, N);

    // fused layer-2 aggregation + pooling
    k_agg2pool<<<(N + 255) / 256, 256>>>(batch, N);
    k_final<<<(N_GRAPHS + 255) / 256, 256>>>(b2, out);
}